// round 14
// baseline (speedup 1.0000x reference)
#include <cuda_runtime.h>
#include <cuda_fp16.h>

#define C_DIM   64
#define TPB     128
#define MARGIN_F 0.01f
#define MAX_BLOCKS 8192

// w2(i) = 0.5/(C-i): per-gap weight under relu = (d + |d|)/2. 1/B applied at end.
__host__ __device__ constexpr float W2f(int i)  { return 0.5f / (float)(C_DIM - i); }
// Coefficient of prefix P[x] in telescoped sum_i w2(i)*T_i (gap-set-restricted).
__host__ __device__ constexpr float CPXf(int x) { return -(W2f(x + 1) + W2f(63 - x)); }
__host__ __device__ constexpr float W2SUM_E() {
    float s = 0.0f; for (int i = 2; i < C_DIM; i += 2) s += W2f(i); return s;
}
__host__ __device__ constexpr float W2SUM_O() {
    float s = 0.0f; for (int i = 1; i < C_DIM; i += 2) s += W2f(i); return s;
}

__device__ float        g_partials[MAX_BLOCKS];
__device__ unsigned int g_sem = 0;

// Core |d| sweep over gaps {START, START+2, ...}: packed half2 covers both rows.
template <int START>
__device__ __forceinline__ void gap_sweep(const __half2* a2, float& totalA, float& totalB)
{
    const __half2 HZ = __floats2half2_rn(0.0f, 0.0f);
    #pragma unroll
    for (int i = START; i < C_DIM; i += 2) {
        __half2 c0 = HZ, c1 = HZ, c2 = HZ, c3 = HZ;
        #pragma unroll
        for (int j = 0; j + i < C_DIM; j += 4) {
            c0 = __hadd2(c0, __habs2(__hsub2(a2[j + i], a2[j])));
            if (j + 1 + i < C_DIM)
                c1 = __hadd2(c1, __habs2(__hsub2(a2[j + 1 + i], a2[j + 1])));
            if (j + 2 + i < C_DIM)
                c2 = __hadd2(c2, __habs2(__hsub2(a2[j + 2 + i], a2[j + 2])));
            if (j + 3 + i < C_DIM)
                c3 = __hadd2(c3, __habs2(__hsub2(a2[j + 3 + i], a2[j + 3])));
        }
        __half2 ts = __hadd2(__hadd2(c0, c1), __hadd2(c2, c3));
        totalA = __fmaf_rn(__low2float(ts),  W2f(i), totalA);   // FFMA-imm
        totalB = __fmaf_rn(__high2float(ts), W2f(i), totalB);
    }
}

// Two threads per row-pair: warp parity selects the gap subset (no divergence).
// 5 CTAs/SM (102-reg cap): grid 1024 -> ~20 resident warps/SM.
__global__ void __launch_bounds__(TPB, 5)
margin_loss_kernel(const float* __restrict__ cand,
                   const float* __restrict__ summ,
                   float* __restrict__ out,
                   int B, int npairs, float invB)
{
    const int gw      = (blockIdx.x * TPB + threadIdx.x) >> 5;   // global warp
    const int lane    = threadIdx.x & 31;
    const int parity  = gw & 1;                                   // warp-uniform
    const int pairIdx = (gw >> 1) * 32 + lane;

    float thread_total = 0.0f;

    if (pairIdx < npairs) {
        const int  rowA = 2 * pairIdx;
        const int  rowB = rowA + 1;
        const bool hasB = (rowB < B);
        const int  rB   = hasB ? rowB : rowA;

        const float4* pa = reinterpret_cast<const float4*>(cand + (size_t)rowA * C_DIM);
        const float4* pb = reinterpret_cast<const float4*>(cand + (size_t)rB   * C_DIM);

        const float sA = summ[rowA];
        const float sB = summ[rB];

        __half2 a2[C_DIM];
        float rsA = 0.0f, rsB = 0.0f;                 // f32 summary relu sums
        float pA = 0.0f, pB = 0.0f;                   // prefix (folded, f32)
        float anEA = 0.0f, anEB = 0.0f;               // telescope, even-gap set
        float anOA = 0.0f, anOB = 0.0f;               // telescope, odd-gap set

        // ---- load, summary (f32), margin fold (f32), prefix/telescope, cvt f16 ----
        #pragma unroll
        for (int i4 = 0; i4 < C_DIM / 4; i4++) {
            float4 va = pa[i4];
            float4 vb = pb[i4];
            float ea[4] = { va.x, va.y, va.z, va.w };
            float eb[4] = { vb.x, vb.y, vb.z, vb.w };
            #pragma unroll
            for (int k = 0; k < 4; k++) {
                const int x = 4 * i4 + k;
                rsA += fmaxf(ea[k] - sA, 0.0f);
                rsB += fmaxf(eb[k] - sB, 0.0f);
                float fa = __fmaf_rn(MARGIN_F, (float)x, ea[k]);
                float fb = __fmaf_rn(MARGIN_F, (float)x, eb[k]);
                pA += fa;
                pB += fb;
                if ((x & 1) == 1 && x <= 61) {        // even-gap set: odd x in [1,61]
                    anEA = __fmaf_rn(CPXf(x), pA, anEA);
                    anEB = __fmaf_rn(CPXf(x), pB, anEB);
                }
                if ((x & 1) == 0 && x <= 62) {        // odd-gap set: even x in [0,62]
                    anOA = __fmaf_rn(CPXf(x), pA, anOA);
                    anOB = __fmaf_rn(CPXf(x), pB, anOB);
                }
                a2[x] = __floats2half2_rn(fa, fb);
            }
        }

        // ---- analytic telescoped Sd part for this thread's gap subset ----
        const float w2s = parity ? W2SUM_O() : W2SUM_E();
        float totalA = (parity ? anOA : anEA) + pA * w2s;
        float totalB = (parity ? anOB : anEB) + pB * w2s;

        // ---- summary term owned by parity-0 threads (balances odd set's +32 ops) ----
        if (parity == 0) {
            totalA = __fmaf_rn(rsA, 1.0f / (float)C_DIM, totalA);
            totalB = __fmaf_rn(rsB, 1.0f / (float)C_DIM, totalB);
        }

        // ---- packed |d| core over this parity's gaps ----
        if (parity)
            gap_sweep<1>(a2, totalA, totalB);
        else
            gap_sweep<2>(a2, totalA, totalB);

        thread_total = totalA + (hasB ? totalB : 0.0f);
    }

    // ---- deterministic block reduction ----
    __shared__ float sred[TPB];
    __shared__ bool  amLast;
    sred[threadIdx.x] = thread_total;
    __syncthreads();
    #pragma unroll
    for (int off = TPB / 2; off > 0; off >>= 1) {
        if (threadIdx.x < off)
            sred[threadIdx.x] += sred[threadIdx.x + off];
        __syncthreads();
    }
    if (threadIdx.x == 0) {
        g_partials[blockIdx.x] = sred[0];
        __threadfence();
        unsigned int v = atomicAdd(&g_sem, 1u);
        amLast = (v == gridDim.x - 1);
    }
    __syncthreads();

    // ---- last arriving block: deterministic final reduce ----
    if (amLast) {
        float v = 0.0f;
        for (int i = threadIdx.x; i < (int)gridDim.x; i += TPB)
            v += g_partials[i];
        sred[threadIdx.x] = v;
        __syncthreads();
        #pragma unroll
        for (int off = TPB / 2; off > 0; off >>= 1) {
            if (threadIdx.x < off)
                sred[threadIdx.x] += sred[threadIdx.x + off];
            __syncthreads();
        }
        if (threadIdx.x == 0) {
            out[0] = sred[0] * invB;
            g_sem = 0;   // reset for next graph replay
        }
    }
}

extern "C" void kernel_launch(void* const* d_in, const int* in_sizes, int n_in,
                              void* d_out, int out_size)
{
    const float* cand = (const float*)d_in[0];   // [B, 64] f32
    const float* summ = (const float*)d_in[1];   // [B]     f32
    float* out = (float*)d_out;

    const int B = in_sizes[1];
    const int npairs   = (B + 1) / 2;
    const int nthreads = 2 * npairs;             // 2 parity threads per row-pair
    int nblocks = (nthreads + TPB - 1) / TPB;
    if (nblocks > MAX_BLOCKS) nblocks = MAX_BLOCKS;
    const float invB = 1.0f / (float)B;

    margin_loss_kernel<<<nblocks, TPB>>>(cand, summ, out, B, npairs, invB);
}

// round 17
// speedup vs baseline: 1.3769x; 1.3769x over previous
#include <cuda_runtime.h>
#include <cuda_fp16.h>

#define C_DIM   64
#define TPB     128
#define MARGIN_F 0.01f
#define MAX_BLOCKS 8192

// w2(i) = 0.5/(C-i): per-gap weight under relu = (d + |d|)/2. 1/B applied at end.
__host__ __device__ constexpr float W2f(int i)  { return 0.5f / (float)(C_DIM - i); }
// Coefficient of prefix P[x] in telescoped sum_i w2(i)*T_i over ALL gaps.
__host__ __device__ constexpr float CPXf(int x) { return -(W2f(x + 1) + W2f(63 - x)); }
__host__ __device__ constexpr float W2SUMf() {
    float s = 0.0f;
    for (int i = 1; i < C_DIM; i++) s += W2f(i);
    return s;
}

__device__ float        g_partials[MAX_BLOCKS];
__device__ unsigned int g_sem = 0;

// Two rows per thread: rows (2t, 2t+1) in the (lo, hi) lanes of half2.
// R12-identical launch config: 128 regs cap, measured no spills.
__global__ void __launch_bounds__(TPB, 4)
margin_loss_kernel(const float* __restrict__ cand,
                   const float* __restrict__ summ,
                   float* __restrict__ out,
                   int B, float invB)
{
    const int t = blockIdx.x * TPB + threadIdx.x;
    const int rowA = 2 * t;
    const int rowB = 2 * t + 1;

    float thread_total = 0.0f;

    if (rowA < B) {
        const bool hasB = (rowB < B);
        const int  rB   = hasB ? rowB : rowA;

        const float4* pa = reinterpret_cast<const float4*>(cand + (size_t)rowA * C_DIM);
        const float4* pb = reinterpret_cast<const float4*>(cand + (size_t)rB   * C_DIM);

        const float sA = summ[rowA];
        const float sB = summ[rB];

        __half2 a2[C_DIM];
        float rsA = 0.0f, rsB = 0.0f;   // f32 summary relu sums
        float pA  = 0.0f, pB  = 0.0f;   // f32 prefix of margin-folded values
        float anA = 0.0f, anB = 0.0f;   // f32 telescoped analytic accumulators

        // ---- load (f32), summary, margin fold, prefix telescope, cvt half2 ----
        // pA/pB/anA/anB die before the core loop: no added core-loop pressure.
        #pragma unroll
        for (int i4 = 0; i4 < C_DIM / 4; i4++) {
            float4 va = pa[i4];
            float4 vb = pb[i4];
            float ea[4] = { va.x, va.y, va.z, va.w };
            float eb[4] = { vb.x, vb.y, vb.z, vb.w };
            #pragma unroll
            for (int k = 0; k < 4; k++) {
                const int x = 4 * i4 + k;
                rsA += fmaxf(ea[k] - sA, 0.0f);
                rsB += fmaxf(eb[k] - sB, 0.0f);
                float fa = __fmaf_rn(MARGIN_F, (float)x, ea[k]);
                float fb = __fmaf_rn(MARGIN_F, (float)x, eb[k]);
                pA += fa;
                pB += fb;
                if (x < 63) {
                    anA = __fmaf_rn(CPXf(x), pA, anA);   // FFMA-imm
                    anB = __fmaf_rn(CPXf(x), pB, anB);
                }
                a2[x] = __floats2half2_rn(fa, fb);
            }
        }

        // ---- analytic parts: summary + telescoped sum_i w2(i)*Sd_i ----
        float totalA = rsA * (1.0f / (float)C_DIM) + anA;
        float totalB = rsB * (1.0f / (float)C_DIM) + anB;
        totalA = __fmaf_rn(pA, W2SUMf(), totalA);
        totalB = __fmaf_rn(pB, W2SUMf(), totalB);

        // ---- core: packed Sum|d| over all gaps; |.| folds into HADD2 operand ----
        #pragma unroll
        for (int i = 1; i < C_DIM; i++) {
            __half2 c0 = __floats2half2_rn(0.0f, 0.0f);
            __half2 c1 = c0, c2 = c0, c3 = c0;
            #pragma unroll
            for (int j = 0; j + i < C_DIM; j += 4) {
                c0 = __hadd2(c0, __habs2(__hsub2(a2[j + i], a2[j])));
                if (j + 1 + i < C_DIM)
                    c1 = __hadd2(c1, __habs2(__hsub2(a2[j + 1 + i], a2[j + 1])));
                if (j + 2 + i < C_DIM)
                    c2 = __hadd2(c2, __habs2(__hsub2(a2[j + 2 + i], a2[j + 2])));
                if (j + 3 + i < C_DIM)
                    c3 = __hadd2(c3, __habs2(__hsub2(a2[j + 3 + i], a2[j + 3])));
            }
            __half2 ts = __hadd2(__hadd2(c0, c1), __hadd2(c2, c3));
            totalA = __fmaf_rn(__low2float(ts),  W2f(i), totalA);   // FFMA-imm
            totalB = __fmaf_rn(__high2float(ts), W2f(i), totalB);
        }

        thread_total = totalA + (hasB ? totalB : 0.0f);
    }

    // ---- deterministic block reduction ----
    __shared__ float sred[TPB];
    __shared__ bool  amLast;
    sred[threadIdx.x] = thread_total;
    __syncthreads();
    #pragma unroll
    for (int off = TPB / 2; off > 0; off >>= 1) {
        if (threadIdx.x < off)
            sred[threadIdx.x] += sred[threadIdx.x + off];
        __syncthreads();
    }
    if (threadIdx.x == 0) {
        g_partials[blockIdx.x] = sred[0];
        __threadfence();
        unsigned int v = atomicAdd(&g_sem, 1u);
        amLast = (v == gridDim.x - 1);
    }
    __syncthreads();

    // ---- last arriving block: deterministic final reduce ----
    if (amLast) {
        float v = 0.0f;
        for (int i = threadIdx.x; i < (int)gridDim.x; i += TPB)
            v += g_partials[i];
        sred[threadIdx.x] = v;
        __syncthreads();
        #pragma unroll
        for (int off = TPB / 2; off > 0; off >>= 1) {
            if (threadIdx.x < off)
                sred[threadIdx.x] += sred[threadIdx.x + off];
            __syncthreads();
        }
        if (threadIdx.x == 0) {
            out[0] = sred[0] * invB;
            g_sem = 0;   // reset for next graph replay
        }
    }
}

extern "C" void kernel_launch(void* const* d_in, const int* in_sizes, int n_in,
                              void* d_out, int out_size)
{
    const float* cand = (const float*)d_in[0];   // [B, 64] f32
    const float* summ = (const float*)d_in[1];   // [B]     f32
    float* out = (float*)d_out;

    const int B = in_sizes[1];
    const int nthreads = (B + 1) / 2;            // 2 rows per thread
    int nblocks = (nthreads + TPB - 1) / TPB;
    if (nblocks > MAX_BLOCKS) nblocks = MAX_BLOCKS;
    const float invB = 1.0f / (float)B;

    margin_loss_kernel<<<nblocks, TPB>>>(cand, summ, out, B, invB);
}